// round 8
// baseline (speedup 1.0000x reference)
#include <cuda_runtime.h>
#include <cuda_bf16.h>
#include <cstdint>

// Problem constants
#define BQ 16
#define DQ 128
#define TQ 4096
#define VQ 1024

#define TILE_M 64
#define TILE_N 128
#define NCHUNK 8
#define MARGIN 3.0f
#define QCAP 4096
#define NTHREADS 256

// Dynamic SMEM layout (bytes) -- total 103424, fits 2 CTAs/SM
#define OFF_RES    0          // 64 x u64 packed (score,idx)
#define OFF_ROWMIN 512        // 64 x u32 running cheap min (order-uint)
#define OFF_QN     768        // queue counter
#define OFF_CSQ    1024       // 1024 floats
#define OFF_AF     5120       // fp32 A [64][128]
#define OFF_AH     37888      // bf16 A tile 16KB (swizzled)
#define OFF_B      54272      // bf16 B tile 32KB (single buffer)
#define OFF_QUEUE  87040      // QCAP x u32
#define SMEM_TOTAL 103424

__device__ float g_csq[VQ];
__device__ __nv_bfloat16 g_ch[VQ * DQ];

// ---------------------------------------------------------------------------
__device__ __forceinline__ uint32_t smem_u32(const void* p) {
    uint32_t a;
    asm("{ .reg .u64 t; cvta.to.shared.u64 t, %1; cvt.u32.u64 %0, t; }"
        : "=r"(a) : "l"(p));
    return a;
}

#define LDMX4(r, addr) \
    asm volatile("ldmatrix.sync.aligned.m8n8.x4.shared.b16 {%0,%1,%2,%3}, [%4];" \
        : "=r"((r)[0]), "=r"((r)[1]), "=r"((r)[2]), "=r"((r)[3]) \
        : "r"(addr))

__device__ __forceinline__ void mma_bf16(float* c, const uint32_t* a,
                                         const uint32_t* b) {
    asm volatile(
        "mma.sync.aligned.m16n8k16.row.col.f32.bf16.bf16.f32 "
        "{%0,%1,%2,%3}, {%4,%5,%6,%7}, {%8,%9}, {%0,%1,%2,%3};"
        : "+f"(c[0]), "+f"(c[1]), "+f"(c[2]), "+f"(c[3])
        : "r"(a[0]), "r"(a[1]), "r"(a[2]), "r"(a[3]), "r"(b[0]), "r"(b[1]));
}

#define CP_ASYNC16(dst, src) \
    asm volatile("cp.async.cg.shared.global [%0], [%1], 16;" \
        :: "r"(dst), "l"(src))
#define CP_COMMIT() asm volatile("cp.async.commit_group;" ::: "memory")
#define CP_WAIT0() asm volatile("cp.async.wait_group 0;" ::: "memory")

// Swizzled byte offset inside a (rows x 128) bf16 tile (256B rows, 16B chunks,
// chunk column XOR'd with row%8 -> conflict-free ldmatrix).
__device__ __forceinline__ uint32_t tswz(int row, int col2b) {
    return (uint32_t)(row * 256 + ((((col2b >> 3) ^ (row & 7)) << 4) |
                                   ((col2b & 7) * 2)));
}

// Order-preserving float <-> uint
__device__ __forceinline__ unsigned fford(float f) {
    unsigned u = __float_as_uint(f);
    return (u & 0x80000000u) ? ~u : (u | 0x80000000u);
}
__device__ __forceinline__ float fford_inv(unsigned u) {
    unsigned b = (u & 0x80000000u) ? (u & 0x7fffffffu) : ~u;
    return __uint_as_float(b);
}

// ---------------------------------------------------------------------------
// Prep: per code row v, csq[v] and bf16-hi conversion. One warp per row.
// ---------------------------------------------------------------------------
__global__ void prep_kernel(const float* __restrict__ cb) {
    int v = (blockIdx.x * blockDim.x + threadIdx.x) >> 5;
    int lane = threadIdx.x & 31;
    if (v >= VQ) return;
    const float4 x4 = *(const float4*)(cb + (size_t)v * DQ + lane * 4);
    float s = x4.x * x4.x + x4.y * x4.y + x4.z * x4.z + x4.w * x4.w;
#pragma unroll
    for (int off = 16; off; off >>= 1)
        s += __shfl_down_sync(0xffffffffu, s, off);
    if (lane == 0) g_csq[v] = s;
    __nv_bfloat162 p0 = __nv_bfloat162(__float2bfloat16(x4.x),
                                       __float2bfloat16(x4.y));
    __nv_bfloat162 p1 = __nv_bfloat162(__float2bfloat16(x4.z),
                                       __float2bfloat16(x4.w));
    *(__nv_bfloat162*)(g_ch + (size_t)v * DQ + lane * 4) = p0;
    *(__nv_bfloat162*)(g_ch + (size_t)v * DQ + lane * 4 + 2) = p1;
}

// ---------------------------------------------------------------------------
// Main: cheap bf16 GEMM screen -> candidate queue -> exact fp32 rescore ->
// codes + fused quantized gather.  256 threads, 8 warps in a 2x4 grid,
// warp tile 32x32, CTA tile 64x128x128, V in 8 chunks. 2 CTAs/SM.
// ---------------------------------------------------------------------------
__global__ void __launch_bounds__(NTHREADS, 2)
vq_kernel(const float* __restrict__ latents, const float* __restrict__ cb,
          float* __restrict__ codes, float* __restrict__ quant) {
    extern __shared__ unsigned char sm[];
    const uint32_t smb = smem_u32(sm);
    const int tid = threadIdx.x;
    const int lane = tid & 31;
    const int wid = tid >> 5;
    const int warp_m = wid & 1;    // 2 m-tiles of 32 rows
    const int warp_n = wid >> 1;   // 4 n-tiles of 32 cols
    const int b = blockIdx.y;
    const int t0 = blockIdx.x * TILE_M;

    unsigned long long* res = (unsigned long long*)(sm + OFF_RES);
    unsigned* rowmin = (unsigned*)(sm + OFF_ROWMIN);
    unsigned* qn = (unsigned*)(sm + OFF_QN);
    float* csq_s = (float*)(sm + OFF_CSQ);
    float* Af = (float*)(sm + OFF_AF);
    unsigned* queue = (unsigned*)(sm + OFF_QUEUE);

    // Prefetch B chunk 0 immediately (overlaps with A conversion below)
    {
        const __nv_bfloat16* src = g_ch;
        for (int i = tid; i < 2048; i += NTHREADS) {
            int n = i >> 4, c = i & 15;
            CP_ASYNC16(smb + OFF_B + tswz(n, c * 8),
                       (const void*)(src + n * DQ + c * 8));
        }
        CP_COMMIT();
    }

    if (tid < TILE_M) {
        res[tid] = ~0ull;
        rowmin[tid] = 0xFFFFFFFFu;
    }
    if (tid == 0) *qn = 0;
    for (int i = tid; i < VQ; i += NTHREADS) csq_s[i] = g_csq[i];

    // A: latents[b][d][t0+t] -> bf16-hi swizzled tile + fp32 copy
    {
        const float* xg = latents + (size_t)b * DQ * TQ + t0;
        for (int idx = tid; idx < DQ * TILE_M; idx += NTHREADS) {
            int d = idx >> 6;      // 0..127
            int t = idx & 63;      // coalesced over t
            float x = xg[(size_t)d * TQ + t];
            *(__nv_bfloat16*)(sm + OFF_AH + tswz(t, d)) = __float2bfloat16(x);
            Af[t * DQ + d] = x;
        }
    }

    // Per-thread ldmatrix constants
    const int arow_in16 = lane & 15;
    const int kca = lane >> 4;
    const int brow_in16 = (lane & 7) | ((lane >> 4) << 3);
    const int kcb = (lane >> 3) & 1;

    int axr[2];
    uint32_t abase[2];
#pragma unroll
    for (int mi = 0; mi < 2; mi++) {
        int row = warp_m * 32 + mi * 16 + arow_in16;
        axr[mi] = row & 7;
        abase[mi] = (uint32_t)(row * 256);
    }
    int bxr[2];
    uint32_t bbase[2];
#pragma unroll
    for (int n4 = 0; n4 < 2; n4++) {
        int row = warp_n * 32 + n4 * 16 + brow_in16;
        bxr[n4] = row & 7;
        bbase[n4] = (uint32_t)(row * 256);
    }

    for (int vc = 0; vc < NCHUNK; vc++) {
        const int v0 = vc * TILE_N;

        CP_WAIT0();
        __syncthreads();   // B[vc] visible to all; A tile ready (vc==0)

        float acc[2][4][4];
#pragma unroll
        for (int mi = 0; mi < 2; mi++)
#pragma unroll
            for (int ni = 0; ni < 4; ni++)
#pragma unroll
                for (int q = 0; q < 4; q++) acc[mi][ni][q] = 0.f;

#pragma unroll
        for (int ks = 0; ks < 8; ks++) {
            uint32_t aH[2][4];
#pragma unroll
            for (int mi = 0; mi < 2; mi++) {
                uint32_t co = (uint32_t)((((ks << 1) | kca) ^ axr[mi]) << 4);
                LDMX4(aH[mi], smb + OFF_AH + abase[mi] + co);
            }
            uint32_t bH[4][2];
#pragma unroll
            for (int n4 = 0; n4 < 2; n4++) {
                uint32_t co = (uint32_t)((((ks << 1) | kcb) ^ bxr[n4]) << 4);
                uint32_t r[4];
                LDMX4(r, smb + OFF_B + bbase[n4] + co);
                bH[n4 * 2][0] = r[0]; bH[n4 * 2][1] = r[1];
                bH[n4 * 2 + 1][0] = r[2]; bH[n4 * 2 + 1][1] = r[3];
            }
#pragma unroll
            for (int mi = 0; mi < 2; mi++)
#pragma unroll
                for (int ni = 0; ni < 4; ni++)
                    mma_bf16(acc[mi][ni], aH[mi], bH[ni]);
        }

        // Convert acc -> cheap scores in place, track per-thread row mins
        float rm[4];
#pragma unroll
        for (int j = 0; j < 4; j++) rm[j] = 3.4e38f;
#pragma unroll
        for (int ni = 0; ni < 4; ni++) {
            int col0 = v0 + warp_n * 32 + ni * 8 + (lane & 3) * 2;
            float cs0 = csq_s[col0], cs1 = csq_s[col0 + 1];
#pragma unroll
            for (int mi = 0; mi < 2; mi++) {
                float* c = acc[mi][ni];
                c[0] = fmaf(-2.f, c[0], cs0);
                c[1] = fmaf(-2.f, c[1], cs1);
                c[2] = fmaf(-2.f, c[2], cs0);
                c[3] = fmaf(-2.f, c[3], cs1);
                float m01 = fminf(c[0], c[1]), m23 = fminf(c[2], c[3]);
                if (m01 < rm[mi * 2]) rm[mi * 2] = m01;
                if (m23 < rm[mi * 2 + 1]) rm[mi * 2 + 1] = m23;
            }
        }
#pragma unroll
        for (int j = 0; j < 4; j++) {
            int row = warp_m * 32 + (j >> 1) * 16 + (j & 1) * 8 + (lane >> 2);
            atomicMin(&rowmin[row], fford(rm[j]));
        }
        __syncthreads();   // rowmin complete; all B ldmatrix reads retired

        // Issue next chunk's B load (overwrites single buffer; overlaps
        // with candidate insertion and the other resident CTA's compute)
        if (vc < NCHUNK - 1) {
            const __nv_bfloat16* src = g_ch + (size_t)(v0 + TILE_N) * DQ;
            for (int i = tid; i < 2048; i += NTHREADS) {
                int n = i >> 4, c = i & 15;
                CP_ASYNC16(smb + OFF_B + tswz(n, c * 8),
                           (const void*)(src + n * DQ + c * 8));
            }
            CP_COMMIT();
        }

        // Insert candidates within MARGIN of running row min
#pragma unroll
        for (int mi = 0; mi < 2; mi++) {
            int rA = warp_m * 32 + mi * 16 + (lane >> 2);
            float thA = fford_inv(rowmin[rA]) + MARGIN;
            float thB = fford_inv(rowmin[rA + 8]) + MARGIN;
#pragma unroll
            for (int ni = 0; ni < 4; ni++) {
                int col0 = v0 + warp_n * 32 + ni * 8 + (lane & 3) * 2;
                const float* c = acc[mi][ni];
                if (c[0] <= thA) {
                    unsigned k = atomicAdd(qn, 1u);
                    if (k < QCAP) queue[k] = ((unsigned)rA << 10) | col0;
                }
                if (c[1] <= thA) {
                    unsigned k = atomicAdd(qn, 1u);
                    if (k < QCAP) queue[k] = ((unsigned)rA << 10) | (col0 + 1);
                }
                if (c[2] <= thB) {
                    unsigned k = atomicAdd(qn, 1u);
                    if (k < QCAP) queue[k] = ((unsigned)(rA + 8) << 10) | col0;
                }
                if (c[3] <= thB) {
                    unsigned k = atomicAdd(qn, 1u);
                    if (k < QCAP) queue[k] = ((unsigned)(rA + 8) << 10) | (col0 + 1);
                }
            }
        }
    }
    __syncthreads();

    // Exact fp32 rescore of candidates: one warp per queue entry
    {
        unsigned n = *qn;
        if (n > QCAP) n = QCAP;
        for (unsigned e = wid; e < n; e += 8) {
            unsigned ent = queue[e];
            int r = ent >> 10;
            int v = ent & 1023;
            const float4 xa = *(const float4*)(Af + r * DQ + lane * 4);
            const float4 ca = *(const float4*)(cb + (size_t)v * DQ + lane * 4);
            float s = xa.x * ca.x + xa.y * ca.y + xa.z * ca.z + xa.w * ca.w;
#pragma unroll
            for (int off = 16; off; off >>= 1)
                s += __shfl_down_sync(0xffffffffu, s, off);
            if (lane == 0) {
                float score = fmaf(-2.f, s, csq_s[v]);
                unsigned long long pk =
                    ((unsigned long long)fford(score) << 32) | (unsigned)v;
                atomicMin(&res[r], pk);
            }
        }
    }
    __syncthreads();

    // Write codes (as float) and fused quantized gather
    if (tid < TILE_M)
        codes[(size_t)b * TQ + t0 + tid] = (float)(unsigned)(res[tid] & 1023u);

    {
        int t = tid & 63;
        int dh = tid >> 6;                 // 0..3: d-quarters
        int v = (int)(res[t] & 1023u);
        const float* crow = cb + (size_t)v * DQ + dh * 32;
        float* q = quant + (size_t)b * DQ * TQ + (size_t)(dh * 32) * TQ + t0 + t;
#pragma unroll
        for (int i = 0; i < 8; i++) {
            float4 c4 = *(const float4*)(crow + i * 4);
            q[(i * 4 + 0) * TQ] = c4.x;
            q[(i * 4 + 1) * TQ] = c4.y;
            q[(i * 4 + 2) * TQ] = c4.z;
            q[(i * 4 + 3) * TQ] = c4.w;
        }
    }
}

// ---------------------------------------------------------------------------
extern "C" void kernel_launch(void* const* d_in, const int* in_sizes, int n_in,
                              void* d_out, int out_size) {
    const float* latents = (const float*)d_in[0];   // (B, D, T) fp32
    const float* codebook = (const float*)d_in[1];  // (V, D)    fp32

    float* codes = (float*)d_out;             // B*T floats
    float* quant = (float*)d_out + BQ * TQ;   // B*D*T floats

    cudaFuncSetAttribute(vq_kernel,
                         cudaFuncAttributeMaxDynamicSharedMemorySize,
                         SMEM_TOTAL);

    prep_kernel<<<(VQ * 32) / 256, 256>>>(codebook);

    dim3 grid(TQ / TILE_M, BQ);   // (64, 16) = 1024 blocks
    vq_kernel<<<grid, NTHREADS, SMEM_TOTAL>>>(latents, codebook, codes, quant);
}

// round 9
// speedup vs baseline: 1.0227x; 1.0227x over previous
#include <cuda_runtime.h>
#include <cuda_bf16.h>
#include <cstdint>

// Problem constants
#define BQ 16
#define DQ 128
#define TQ 4096
#define VQ 1024

#define TILE_M 128
#define TILE_N 128
#define NCHUNK 8
#define MARGIN 3.0f
#define QCAP 4096
#define NTHREADS 512

// Dynamic SMEM layout (bytes)
#define OFF_RES    0          // 128 x u64 packed (score,idx)
#define OFF_ROWMIN 1024       // 128 x u32 (order-uint running cheap min)
#define OFF_QN     1536       // queue counter
#define OFF_CSQ    2048       // 1024 floats
#define OFF_QUEUE  6144       // QCAP x u32 (16KB)
#define OFF_AF     22528      // fp32 A [128][AF_STRIDE]
#define AF_STRIDE  132
#define OFF_AH     90112      // bf16 A tile 32KB (swizzled)
#define OFF_B      122880     // bf16 B tiles, 3 x 32KB (triple buffer)
#define BTILE      32768
#define SMEM_TOTAL 221184

__device__ float g_csq[VQ];
__device__ __nv_bfloat16 g_ch[VQ * DQ];

// ---------------------------------------------------------------------------
__device__ __forceinline__ uint32_t smem_u32(const void* p) {
    uint32_t a;
    asm("{ .reg .u64 t; cvta.to.shared.u64 t, %1; cvt.u32.u64 %0, t; }"
        : "=r"(a) : "l"(p));
    return a;
}

#define LDMX4(r, addr) \
    asm volatile("ldmatrix.sync.aligned.m8n8.x4.shared.b16 {%0,%1,%2,%3}, [%4];" \
        : "=r"((r)[0]), "=r"((r)[1]), "=r"((r)[2]), "=r"((r)[3]) \
        : "r"(addr))

__device__ __forceinline__ void mma_bf16(float* c, const uint32_t* a,
                                         const uint32_t* b) {
    asm volatile(
        "mma.sync.aligned.m16n8k16.row.col.f32.bf16.bf16.f32 "
        "{%0,%1,%2,%3}, {%4,%5,%6,%7}, {%8,%9}, {%0,%1,%2,%3};"
        : "+f"(c[0]), "+f"(c[1]), "+f"(c[2]), "+f"(c[3])
        : "r"(a[0]), "r"(a[1]), "r"(a[2]), "r"(a[3]), "r"(b[0]), "r"(b[1]));
}

#define CP_ASYNC16(dst, src) \
    asm volatile("cp.async.cg.shared.global [%0], [%1], 16;" \
        :: "r"(dst), "l"(src))
#define CP_COMMIT() asm volatile("cp.async.commit_group;" ::: "memory")
#define CP_WAIT2() asm volatile("cp.async.wait_group 2;" ::: "memory")

// Swizzled byte offset inside a (rows x 128) bf16 tile (256B rows, 16B chunks,
// chunk column XOR'd with row%8 -> conflict-free ldmatrix).
__device__ __forceinline__ uint32_t tswz(int row, int col2b) {
    return (uint32_t)(row * 256 + ((((col2b >> 3) ^ (row & 7)) << 4) |
                                   ((col2b & 7) * 2)));
}

// Order-preserving float <-> uint
__device__ __forceinline__ unsigned fford(float f) {
    unsigned u = __float_as_uint(f);
    return (u & 0x80000000u) ? ~u : (u | 0x80000000u);
}
__device__ __forceinline__ float fford_inv(unsigned u) {
    unsigned b = (u & 0x80000000u) ? (u & 0x7fffffffu) : ~u;
    return __uint_as_float(b);
}

// ---------------------------------------------------------------------------
// Prep: per code row v, csq[v] and bf16-hi conversion. One warp per row.
// ---------------------------------------------------------------------------
__global__ void prep_kernel(const float* __restrict__ cb) {
    int v = (blockIdx.x * blockDim.x + threadIdx.x) >> 5;
    int lane = threadIdx.x & 31;
    if (v >= VQ) return;
    const float4 x4 = *(const float4*)(cb + (size_t)v * DQ + lane * 4);
    float s = x4.x * x4.x + x4.y * x4.y + x4.z * x4.z + x4.w * x4.w;
#pragma unroll
    for (int off = 16; off; off >>= 1)
        s += __shfl_down_sync(0xffffffffu, s, off);
    if (lane == 0) g_csq[v] = s;
    __nv_bfloat162 p0 = __nv_bfloat162(__float2bfloat16(x4.x),
                                       __float2bfloat16(x4.y));
    __nv_bfloat162 p1 = __nv_bfloat162(__float2bfloat16(x4.z),
                                       __float2bfloat16(x4.w));
    *(__nv_bfloat162*)(g_ch + (size_t)v * DQ + lane * 4) = p0;
    *(__nv_bfloat162*)(g_ch + (size_t)v * DQ + lane * 4 + 2) = p1;
}

// ---------------------------------------------------------------------------
// Main: cheap bf16 GEMM screen -> candidate queue -> exact fp32 rescore ->
// codes + fused quantized gather.  512 threads, 16 warps (4x4), warp tile
// 32x32, CTA tile 128x128x128, V in 8 chunks, triple-buffered B, ONE
// syncthreads per chunk (rowmin uses barrier-free monotone atomics).
// ---------------------------------------------------------------------------
__global__ void __launch_bounds__(NTHREADS, 1)
vq_kernel(const float* __restrict__ latents, const float* __restrict__ cb,
          float* __restrict__ codes, float* __restrict__ quant) {
    extern __shared__ unsigned char sm[];
    const uint32_t smb = smem_u32(sm);
    const int tid = threadIdx.x;
    const int lane = tid & 31;
    const int wid = tid >> 5;
    const int warp_m = wid & 3;    // 4 m-tiles of 32 rows
    const int warp_n = wid >> 2;   // 4 n-tiles of 32 cols
    const int b = blockIdx.y;
    const int t0 = blockIdx.x * TILE_M;

    unsigned long long* res = (unsigned long long*)(sm + OFF_RES);
    unsigned* rowmin = (unsigned*)(sm + OFF_ROWMIN);
    unsigned* qn = (unsigned*)(sm + OFF_QN);
    float* csq_s = (float*)(sm + OFF_CSQ);
    float* Af = (float*)(sm + OFF_AF);
    unsigned* queue = (unsigned*)(sm + OFF_QUEUE);

    // Prefetch B chunks 0 and 1 (two committed groups)
#pragma unroll
    for (int pc = 0; pc < 2; pc++) {
        const __nv_bfloat16* src = g_ch + (size_t)pc * TILE_N * DQ;
        uint32_t dbase = smb + OFF_B + pc * BTILE;
        for (int i = tid; i < 2048; i += NTHREADS) {
            int n = i >> 4, c = i & 15;
            CP_ASYNC16(dbase + tswz(n, c * 8),
                       (const void*)(src + n * DQ + c * 8));
        }
        CP_COMMIT();
    }

    if (tid < TILE_M) {
        res[tid] = ~0ull;
        rowmin[tid] = 0xFFFFFFFFu;
    }
    if (tid == 0) *qn = 0;
    for (int i = tid; i < VQ; i += NTHREADS) csq_s[i] = g_csq[i];

    // A: latents[b][d][t0+t] -> bf16-hi swizzled tile + fp32 copy
    {
        const float* xg = latents + (size_t)b * DQ * TQ + t0;
        for (int idx = tid; idx < DQ * TILE_M; idx += NTHREADS) {
            int d = idx >> 7;
            int t = idx & 127;     // coalesced over t
            float x = xg[(size_t)d * TQ + t];
            *(__nv_bfloat16*)(sm + OFF_AH + tswz(t, d)) = __float2bfloat16(x);
            Af[t * AF_STRIDE + d] = x;
        }
    }

    // Per-thread ldmatrix constants (layout validated in R5-R8)
    const int arow_in16 = lane & 15;
    const int kca = lane >> 4;
    const int brow_in16 = (lane & 7) | ((lane >> 4) << 3);
    const int kcb = (lane >> 3) & 1;

    int axr[2];
    uint32_t abase[2];
#pragma unroll
    for (int mi = 0; mi < 2; mi++) {
        int row = warp_m * 32 + mi * 16 + arow_in16;
        axr[mi] = row & 7;
        abase[mi] = (uint32_t)(row * 256);
    }
    int bxr[2];
    uint32_t bbase[2];
#pragma unroll
    for (int n4 = 0; n4 < 2; n4++) {
        int row = warp_n * 32 + n4 * 16 + brow_in16;
        bxr[n4] = row & 7;
        bbase[n4] = (uint32_t)(row * 256);
    }

    for (int vc = 0; vc < NCHUNK; vc++) {
        const int v0 = vc * TILE_N;

        // Prefetch chunk vc+2 into buffer (vc+2)%3; empty commit at tail
        // keeps the outstanding-group count invariant for CP_WAIT2.
        if (vc + 2 < NCHUNK) {
            const __nv_bfloat16* src = g_ch + (size_t)(v0 + 2 * TILE_N) * DQ;
            uint32_t dbase = smb + OFF_B + ((vc + 2) % 3) * BTILE;
            for (int i = tid; i < 2048; i += NTHREADS) {
                int n = i >> 4, c = i & 15;
                CP_ASYNC16(dbase + tswz(n, c * 8),
                           (const void*)(src + n * DQ + c * 8));
            }
        }
        CP_COMMIT();
        CP_WAIT2();        // chunk vc's group complete
        __syncthreads();   // B[vc] visible; all warps past chunk vc-1 reads

        float acc[2][4][4];
#pragma unroll
        for (int mi = 0; mi < 2; mi++)
#pragma unroll
            for (int ni = 0; ni < 4; ni++)
#pragma unroll
                for (int q = 0; q < 4; q++) acc[mi][ni][q] = 0.f;

        const uint32_t bsm = smb + OFF_B + (vc % 3) * BTILE;
#pragma unroll
        for (int ks = 0; ks < 8; ks++) {
            uint32_t aH[2][4];
#pragma unroll
            for (int mi = 0; mi < 2; mi++) {
                uint32_t co = (uint32_t)((((ks << 1) | kca) ^ axr[mi]) << 4);
                LDMX4(aH[mi], smb + OFF_AH + abase[mi] + co);
            }
            uint32_t bH[4][2];
#pragma unroll
            for (int n4 = 0; n4 < 2; n4++) {
                uint32_t co = (uint32_t)((((ks << 1) | kcb) ^ bxr[n4]) << 4);
                uint32_t r[4];
                LDMX4(r, bsm + bbase[n4] + co);
                bH[n4 * 2][0] = r[0]; bH[n4 * 2][1] = r[1];
                bH[n4 * 2 + 1][0] = r[2]; bH[n4 * 2 + 1][1] = r[3];
            }
#pragma unroll
            for (int mi = 0; mi < 2; mi++)
#pragma unroll
                for (int ni = 0; ni < 4; ni++)
                    mma_bf16(acc[mi][ni], aH[mi], bH[ni]);
        }

        // Convert acc -> cheap scores in place, track per-thread row mins
        float rm[4];
#pragma unroll
        for (int j = 0; j < 4; j++) rm[j] = 3.4e38f;
#pragma unroll
        for (int ni = 0; ni < 4; ni++) {
            int col0 = v0 + warp_n * 32 + ni * 8 + (lane & 3) * 2;
            float cs0 = csq_s[col0], cs1 = csq_s[col0 + 1];
#pragma unroll
            for (int mi = 0; mi < 2; mi++) {
                float* c = acc[mi][ni];
                c[0] = fmaf(-2.f, c[0], cs0);
                c[1] = fmaf(-2.f, c[1], cs1);
                c[2] = fmaf(-2.f, c[2], cs0);
                c[3] = fmaf(-2.f, c[3], cs1);
                float m01 = fminf(c[0], c[1]), m23 = fminf(c[2], c[3]);
                if (m01 < rm[mi * 2]) rm[mi * 2] = m01;
                if (m23 < rm[mi * 2 + 1]) rm[mi * 2 + 1] = m23;
            }
        }
        // rowmin is monotone-decreasing; no barrier needed. A stale (higher)
        // read only loosens the threshold (safe superset). The thread that
        // wrote a row's true min reads its own update -> min always queued.
#pragma unroll
        for (int j = 0; j < 4; j++) {
            int row = warp_m * 32 + (j >> 1) * 16 + (j & 1) * 8 + (lane >> 2);
            atomicMin(&rowmin[row], fford(rm[j]));
        }

        // Insert candidates within MARGIN of running row min
#pragma unroll
        for (int mi = 0; mi < 2; mi++) {
            int rA = warp_m * 32 + mi * 16 + (lane >> 2);
            float thA = fford_inv(rowmin[rA]) + MARGIN;
            float thB = fford_inv(rowmin[rA + 8]) + MARGIN;
#pragma unroll
            for (int ni = 0; ni < 4; ni++) {
                int col0 = v0 + warp_n * 32 + ni * 8 + (lane & 3) * 2;
                const float* c = acc[mi][ni];
                if (c[0] <= thA) {
                    unsigned k = atomicAdd(qn, 1u);
                    if (k < QCAP) queue[k] = ((unsigned)rA << 10) | col0;
                }
                if (c[1] <= thA) {
                    unsigned k = atomicAdd(qn, 1u);
                    if (k < QCAP) queue[k] = ((unsigned)rA << 10) | (col0 + 1);
                }
                if (c[2] <= thB) {
                    unsigned k = atomicAdd(qn, 1u);
                    if (k < QCAP) queue[k] = ((unsigned)(rA + 8) << 10) | col0;
                }
                if (c[3] <= thB) {
                    unsigned k = atomicAdd(qn, 1u);
                    if (k < QCAP) queue[k] = ((unsigned)(rA + 8) << 10) | (col0 + 1);
                }
            }
        }
    }
    __syncthreads();

    // Exact fp32 rescore of candidates: one warp per queue entry
    {
        unsigned n = *qn;
        if (n > QCAP) n = QCAP;
        for (unsigned e = wid; e < n; e += 16) {
            unsigned ent = queue[e];
            int r = ent >> 10;
            int v = ent & 1023;
            const float4 xa = *(const float4*)(Af + r * AF_STRIDE + lane * 4);
            const float4 ca = *(const float4*)(cb + (size_t)v * DQ + lane * 4);
            float s = xa.x * ca.x + xa.y * ca.y + xa.z * ca.z + xa.w * ca.w;
#pragma unroll
            for (int off = 16; off; off >>= 1)
                s += __shfl_down_sync(0xffffffffu, s, off);
            if (lane == 0) {
                float score = fmaf(-2.f, s, csq_s[v]);
                unsigned long long pk =
                    ((unsigned long long)fford(score) << 32) | (unsigned)v;
                atomicMin(&res[r], pk);
            }
        }
    }
    __syncthreads();

    // Write codes (as float) and fused quantized gather
    if (tid < TILE_M)
        codes[(size_t)b * TQ + t0 + tid] = (float)(unsigned)(res[tid] & 1023u);

    {
        int t = tid & 127;
        int dh = tid >> 7;                 // 0..3: d-quarters
        int v = (int)(res[t] & 1023u);
        const float* crow = cb + (size_t)v * DQ + dh * 32;
        float* q = quant + (size_t)b * DQ * TQ + (size_t)(dh * 32) * TQ + t0 + t;
#pragma unroll
        for (int i = 0; i < 8; i++) {
            float4 c4 = *(const float4*)(crow + i * 4);
            q[(i * 4 + 0) * TQ] = c4.x;
            q[(i * 4 + 1) * TQ] = c4.y;
            q[(i * 4 + 2) * TQ] = c4.z;
            q[(i * 4 + 3) * TQ] = c4.w;
        }
    }
}

// ---------------------------------------------------------------------------
extern "C" void kernel_launch(void* const* d_in, const int* in_sizes, int n_in,
                              void* d_out, int out_size) {
    const float* latents = (const float*)d_in[0];   // (B, D, T) fp32
    const float* codebook = (const float*)d_in[1];  // (V, D)    fp32

    float* codes = (float*)d_out;             // B*T floats
    float* quant = (float*)d_out + BQ * TQ;   // B*D*T floats

    cudaFuncSetAttribute(vq_kernel,
                         cudaFuncAttributeMaxDynamicSharedMemorySize,
                         SMEM_TOTAL);

    prep_kernel<<<(VQ * 32) / 256, 256>>>(codebook);

    dim3 grid(TQ / TILE_M, BQ);   // (32, 16) = 512 blocks
    vq_kernel<<<grid, NTHREADS, SMEM_TOTAL>>>(latents, codebook, codes, quant);
}